// round 6
// baseline (speedup 1.0000x reference)
#include <cuda_runtime.h>
#include <cstddef>

// ---------------------------------------------------------------------------
// Shapes (fixed):
// prev/next feat : [8, 32, 48, 48, 48] f32
// phi            : [8, 1, 96, 96, 96]  f32
// stream         : [8, 3, 96, 96, 96]  f32
// out (f32, concatenated): corr[8,27,48^3], vel/vphi/vstr [8,3,94^3]
// ---------------------------------------------------------------------------

namespace {
constexpr int C  = 32;
constexpr int D  = 48;
constexpr int SX = D * D;               // 2304
constexpr int SY = D;                   // 48
constexpr long SC  = (long)D * D * D;   // 110592
constexpr long SBF = (long)C * SC;

constexpr int H = 96;
constexpr int O = 94;
constexpr long HS = (long)H * H * H;    // 884736
constexpr long OS = (long)O * O * O;    // 830584

constexpr long CORR_ELEMS = 8L * 27 * SC;
constexpr long VEL_ELEMS  = 8L * 3 * OS;

// fused-grid block populations
constexpr int N_CORR  = 48 * 3 * 8;          // 1152  (x, y-tile of 16, b)
constexpr int JT      = 12;                  // ceil(94/8) j-tiles
constexpr int N_VEL   = JT * O * 8;          // 9024  (j-tile, i, b)
constexpr int N_TOTAL = N_CORR + N_VEL;      // 10176
}

// ---------------------------------------------------------------------------
// corr path: thread = (b, x, y, z4), 4 contiguous z per thread.
// Only 9 distinct (dx,dy) correlations; replicated 3x with z-edge masks.
// ---------------------------------------------------------------------------
__device__ __forceinline__ void corr_block(int idx, int tid,
                                           const float* __restrict__ prev,
                                           const float* __restrict__ nxt,
                                           float* __restrict__ out) {
    const int z4 = tid % 12;
    const int yi = tid / 12;               // 0..15
    const int x  = idx % D;
    const int yt = (idx / D) % 3;
    const int b  = idx / (D * 3);
    const int y  = yt * 16 + yi;
    const int z  = z4 * 4;

    const size_t base = (size_t)b * SBF + (size_t)x * SX + (size_t)y * SY + z;

    bool vx[3], vy[3];
    vx[0] = (x > 0); vx[1] = true; vx[2] = (x < D - 1);
    vy[0] = (y > 0); vy[1] = true; vy[2] = (y < D - 1);

    float4 acc[9];
    #pragma unroll
    for (int d = 0; d < 9; d++) acc[d] = make_float4(0.f, 0.f, 0.f, 0.f);

    #pragma unroll 4
    for (int c = 0; c < C; c++) {
        const size_t cb = base + (size_t)c * SC;
        const float4 p = *reinterpret_cast<const float4*>(prev + cb);
        const float* nb = nxt + cb;
        #pragma unroll
        for (int ix = 0; ix < 3; ix++) {
            #pragma unroll
            for (int iy = 0; iy < 3; iy++) {
                float4 n = make_float4(0.f, 0.f, 0.f, 0.f);
                if (vx[ix] && vy[iy])
                    n = *reinterpret_cast<const float4*>(
                        nb + (ix - 1) * SX + (iy - 1) * SY);
                const int d = ix * 3 + iy;
                acc[d].x += p.x * n.x;
                acc[d].y += p.y * n.y;
                acc[d].z += p.z * n.z;
                acc[d].w += p.w * n.w;
            }
        }
    }

    const float inv = 1.0f / 32.0f;
    const size_t ob = (size_t)b * 27 * SC + (size_t)x * SX + (size_t)y * SY + z;

    #pragma unroll
    for (int d = 0; d < 9; d++) {
        float4 v = acc[d];
        v.x *= inv; v.y *= inv; v.z *= inv; v.w *= inv;

        *reinterpret_cast<float4*>(out + ob + (size_t)(9 + d) * SC) = v;

        float4 vm = v;                      // k=-1: zero z==47
        if (z4 == 11) vm.w = 0.f;
        *reinterpret_cast<float4*>(out + ob + (size_t)d * SC) = vm;

        float4 vp = v;                      // k=+1: zero z==0
        if (z4 == 0) vp.x = 0.f;
        *reinterpret_cast<float4*>(out + ob + (size_t)(18 + d) * SC) = vp;
    }
}

// ---------------------------------------------------------------------------
// vel path: thread = (b, i, j, k4) computing 4 contiguous k outputs.
// 24 groups x 4 = 96 slots but only 94 valid: the tail group (k4==23)
// computes/stores only its first 2 outputs (k=92,93). All float4 input
// loads stay inside the tensor (max index 884,643 < 884,736 per batch).
// Output rows are 94 long -> float2 stores (8B aligned), tail masked.
// ---------------------------------------------------------------------------
__device__ __forceinline__ size_t rH(int x, int y) {
    return ((size_t)x * H + y) * H;
}

__device__ __forceinline__ void ld8(const float* __restrict__ row, int k,
                                    float e[8]) {
    const float4 a = *reinterpret_cast<const float4*>(row + k);
    const float4 b = *reinterpret_cast<const float4*>(row + k + 4);
    e[0] = a.x; e[1] = a.y; e[2] = a.z; e[3] = a.w;
    e[4] = b.x; e[5] = b.y; e[6] = b.z; e[7] = b.w;
}

__device__ __forceinline__ void st2(float* __restrict__ p, float a, float b) {
    *reinterpret_cast<float2*>(p) = make_float2(a, b);
}

__device__ __forceinline__ void vel_block(int idx, int tid,
                                          const float* __restrict__ phi,
                                          const float* __restrict__ stream,
                                          float* __restrict__ vel,
                                          float* __restrict__ vphi,
                                          float* __restrict__ vstr) {
    const int k4 = tid % 24;
    const int jy = tid / 24;               // 0..7
    const int jt = idx % JT;
    const int i  = (idx / JT) % O;
    const int b  = idx / (JT * O);
    const int j  = jt * 8 + jy;
    if (j >= O) return;
    const int k = k4 * 4;
    const bool full = (k4 != 23);          // tail group: only k=92,93 valid

    const float* P  = phi + (size_t)b * HS;
    const float* s0 = stream + (size_t)b * 3 * HS;
    const float* s1 = s0 + HS;
    const float* s2 = s0 + 2 * HS;

    float pu[4], pv[4], pw[4], su[4], sv[4], sw[4];
    float e[8];

    // ---- phi ----
    ld8(P + rH(i + 1, j + 1), k, e);
    #pragma unroll
    for (int t = 0; t < 4; t++) pu[t] = 0.5f * (e[t + 2] - e[t]);
    ld8(P + rH(i + 1, j + 2), k, e);
    #pragma unroll
    for (int t = 0; t < 4; t++) pv[t] = e[t + 1];
    ld8(P + rH(i + 1, j), k, e);
    #pragma unroll
    for (int t = 0; t < 4; t++) pv[t] = 0.5f * (pv[t] - e[t + 1]);
    ld8(P + rH(i + 2, j + 1), k, e);
    #pragma unroll
    for (int t = 0; t < 4; t++) pw[t] = e[t + 1];
    ld8(P + rH(i, j + 1), k, e);
    #pragma unroll
    for (int t = 0; t < 4; t++) pw[t] = 0.5f * (pw[t] - e[t + 1]);

    // ---- s1 rows ----
    ld8(s1 + rH(i + 2, j + 1), k, e);
    #pragma unroll
    for (int t = 0; t < 4; t++) su[t] = e[t] + e[t + 1];
    ld8(s1 + rH(i + 1, j + 1), k, e);
    #pragma unroll
    for (int t = 0; t < 4; t++) {
        su[t] -= e[t] + e[t + 1];
        sw[t]  = e[t + 1] - e[t + 2];
    }
    ld8(s1 + rH(i, j + 1), k, e);
    #pragma unroll
    for (int t = 0; t < 4; t++) sw[t] += e[t + 1] - e[t + 2];

    // ---- s0 rows ----
    ld8(s0 + rH(i + 1, j + 2), k, e);
    #pragma unroll
    for (int t = 0; t < 4; t++) su[t] -= e[t] + e[t + 1];
    ld8(s0 + rH(i + 1, j + 1), k, e);
    #pragma unroll
    for (int t = 0; t < 4; t++) {
        su[t] += e[t] + e[t + 1];
        sv[t]  = e[t + 2] - e[t + 1];
    }
    ld8(s0 + rH(i + 1, j), k, e);
    #pragma unroll
    for (int t = 0; t < 4; t++) sv[t] += e[t + 2] - e[t + 1];

    // ---- s2 rows ----
    ld8(s2 + rH(i + 2, j), k, e);
    #pragma unroll
    for (int t = 0; t < 4; t++) sv[t] -= e[t + 1];
    ld8(s2 + rH(i + 2, j + 1), k, e);
    #pragma unroll
    for (int t = 0; t < 4; t++) sv[t] -= e[t + 1];
    ld8(s2 + rH(i + 1, j), k, e);
    #pragma unroll
    for (int t = 0; t < 4; t++) sv[t] += e[t + 1];
    ld8(s2 + rH(i + 1, j + 1), k, e);
    #pragma unroll
    for (int t = 0; t < 4; t++) {
        sv[t] += e[t + 1];
        sw[t] -= e[t + 1];
    }
    ld8(s2 + rH(i, j + 2), k, e);
    #pragma unroll
    for (int t = 0; t < 4; t++) sw[t] += e[t + 1];
    ld8(s2 + rH(i, j + 1), k, e);
    #pragma unroll
    for (int t = 0; t < 4; t++) sw[t] -= e[t + 1];
    ld8(s2 + rH(i + 1, j + 2), k, e);
    #pragma unroll
    for (int t = 0; t < 4; t++) sw[t] += e[t + 1];

    #pragma unroll
    for (int t = 0; t < 4; t++) {
        su[t] *= 0.5f; sv[t] *= 0.5f; sw[t] *= 0.5f;
    }

    const size_t o0 = (((size_t)(b * 3) * O + i) * O + j) * O + k;

    st2(vphi + o0,          pu[0], pu[1]);
    st2(vphi + o0 + OS,     pv[0], pv[1]);
    st2(vphi + o0 + 2 * OS, pw[0], pw[1]);
    st2(vstr + o0,          su[0], su[1]);
    st2(vstr + o0 + OS,     sv[0], sv[1]);
    st2(vstr + o0 + 2 * OS, sw[0], sw[1]);
    st2(vel  + o0,          pu[0] + su[0], pu[1] + su[1]);
    st2(vel  + o0 + OS,     pv[0] + sv[0], pv[1] + sv[1]);
    st2(vel  + o0 + 2 * OS, pw[0] + sw[0], pw[1] + sw[1]);

    if (full) {
        st2(vphi + o0 + 2,          pu[2], pu[3]);
        st2(vphi + o0 + OS + 2,     pv[2], pv[3]);
        st2(vphi + o0 + 2 * OS + 2, pw[2], pw[3]);
        st2(vstr + o0 + 2,          su[2], su[3]);
        st2(vstr + o0 + OS + 2,     sv[2], sv[3]);
        st2(vstr + o0 + 2 * OS + 2, sw[2], sw[3]);
        st2(vel  + o0 + 2,          pu[2] + su[2], pu[3] + su[3]);
        st2(vel  + o0 + OS + 2,     pv[2] + sv[2], pv[3] + sv[3]);
        st2(vel  + o0 + 2 * OS + 2, pw[2] + sw[2], pw[3] + sw[3]);
    }
}

// ---------------------------------------------------------------------------
// Fused kernel: interleave corr and vel blocks across the grid so the two
// phases (read-heavy vs write-heavy) share HBM concurrently.
// ---------------------------------------------------------------------------
__global__ __launch_bounds__(192)
void fused_kernel(const float* __restrict__ prev,
                  const float* __restrict__ nxt,
                  const float* __restrict__ phi,
                  const float* __restrict__ stream,
                  float* __restrict__ corr,
                  float* __restrict__ vel,
                  float* __restrict__ vphi,
                  float* __restrict__ vstr) {
    const int bid = blockIdx.x;
    const int tid = threadIdx.x;
    const int f0 = (int)((long)bid * N_CORR / N_TOTAL);
    const int f1 = (int)((long)(bid + 1) * N_CORR / N_TOTAL);
    if (f1 > f0) {
        corr_block(f0, tid, prev, nxt, corr);
    } else {
        vel_block(bid - f0, tid, phi, stream, vel, vphi, vstr);
    }
}

// ---------------------------------------------------------------------------
extern "C" void kernel_launch(void* const* d_in, const int* in_sizes, int n_in,
                              void* d_out, int out_size) {
    const float* prev   = (const float*)d_in[0];
    const float* nxt    = (const float*)d_in[1];
    const float* phi    = (const float*)d_in[2];
    const float* stream = (const float*)d_in[3];

    float* out  = (float*)d_out;
    float* corr = out;
    float* vel  = out + CORR_ELEMS;
    float* vphi = vel + VEL_ELEMS;
    float* vstr = vphi + VEL_ELEMS;

    fused_kernel<<<N_TOTAL, 192>>>(prev, nxt, phi, stream,
                                   corr, vel, vphi, vstr);
}

// round 8
// speedup vs baseline: 1.1845x; 1.1845x over previous
#include <cuda_runtime.h>
#include <cstddef>

// ---------------------------------------------------------------------------
// Shapes (fixed):
// prev/next feat : [8, 32, 48, 48, 48] f32
// phi            : [8, 1, 96, 96, 96]  f32
// stream         : [8, 3, 96, 96, 96]  f32
// out (f32, concatenated): corr[8,27,48^3], vel/vphi/vstr [8,3,94^3]
// ---------------------------------------------------------------------------

namespace {
constexpr int C  = 32;
constexpr int D  = 48;
constexpr int SX = D * D;               // 2304
constexpr int SY = D;                   // 48
constexpr long SC  = (long)D * D * D;   // 110592
constexpr long SBF = (long)C * SC;

constexpr int H = 96;
constexpr int O = 94;
constexpr long HS = (long)H * H * H;    // 884736
constexpr long OS = (long)O * O * O;    // 830584

constexpr long CORR_ELEMS = 8L * 27 * SC;
constexpr long VEL_ELEMS  = 8L * 3 * OS;

constexpr int JT = 12;                  // ceil(94/8) j-tiles for vel grid
}

// ---------------------------------------------------------------------------
// Kernel 1: correlation (identical to the proven R1 version).
// Thread = (b, x, y, z4), 4 contiguous z per thread. Only 9 distinct (dx,dy)
// correlations; written 3x with z-edge masks.
// ---------------------------------------------------------------------------
__global__ __launch_bounds__(192)
void corr_kernel(const float* __restrict__ prev,
                 const float* __restrict__ nxt,
                 float* __restrict__ out) {
    const int z4 = threadIdx.x;                       // 0..11
    const int y  = blockIdx.y * blockDim.y + threadIdx.y;
    const int x  = blockIdx.x;
    const int b  = blockIdx.z;
    const int z  = z4 * 4;

    const size_t base = (size_t)b * SBF + (size_t)x * SX + (size_t)y * SY + z;

    bool vx[3], vy[3];
    vx[0] = (x > 0); vx[1] = true; vx[2] = (x < D - 1);
    vy[0] = (y > 0); vy[1] = true; vy[2] = (y < D - 1);

    float4 acc[9];
    #pragma unroll
    for (int d = 0; d < 9; d++) acc[d] = make_float4(0.f, 0.f, 0.f, 0.f);

    #pragma unroll 4
    for (int c = 0; c < C; c++) {
        const size_t cb = base + (size_t)c * SC;
        const float4 p = *reinterpret_cast<const float4*>(prev + cb);
        const float* nb = nxt + cb;
        #pragma unroll
        for (int ix = 0; ix < 3; ix++) {
            #pragma unroll
            for (int iy = 0; iy < 3; iy++) {
                float4 n = make_float4(0.f, 0.f, 0.f, 0.f);
                if (vx[ix] && vy[iy])
                    n = *reinterpret_cast<const float4*>(
                        nb + (ix - 1) * SX + (iy - 1) * SY);
                const int d = ix * 3 + iy;
                acc[d].x += p.x * n.x;
                acc[d].y += p.y * n.y;
                acc[d].z += p.z * n.z;
                acc[d].w += p.w * n.w;
            }
        }
    }

    const float inv = 1.0f / 32.0f;
    const size_t ob = (size_t)b * 27 * SC + (size_t)x * SX + (size_t)y * SY + z;

    #pragma unroll
    for (int d = 0; d < 9; d++) {
        float4 v = acc[d];
        v.x *= inv; v.y *= inv; v.z *= inv; v.w *= inv;

        *reinterpret_cast<float4*>(out + ob + (size_t)(9 + d) * SC) = v;

        float4 vm = v;                      // k=-1: zero z==47
        if (z4 == 11) vm.w = 0.f;
        *reinterpret_cast<float4*>(out + ob + (size_t)d * SC) = vm;

        float4 vp = v;                      // k=+1: zero z==0
        if (z4 == 0) vp.x = 0.f;
        *reinterpret_cast<float4*>(out + ob + (size_t)(18 + d) * SC) = vp;
    }
}

// ---------------------------------------------------------------------------
// Kernel 2: velocities, vectorized (verified correct in R6's fused run).
// Thread = (b, i, j, k4) computing 4 contiguous k outputs; tail group
// (k4==23) stores only k=92,93. All float4 loads in-bounds (max index
// 884,643 < 884,736 per batch). Stores are float2 (rows are 94 long).
// ---------------------------------------------------------------------------
__device__ __forceinline__ size_t rH(int x, int y) {
    return ((size_t)x * H + y) * H;
}

__device__ __forceinline__ void ld8(const float* __restrict__ row, int k,
                                    float e[8]) {
    const float4 a = *reinterpret_cast<const float4*>(row + k);
    const float4 b = *reinterpret_cast<const float4*>(row + k + 4);
    e[0] = a.x; e[1] = a.y; e[2] = a.z; e[3] = a.w;
    e[4] = b.x; e[5] = b.y; e[6] = b.z; e[7] = b.w;
}

__device__ __forceinline__ void st2(float* __restrict__ p, float a, float b) {
    *reinterpret_cast<float2*>(p) = make_float2(a, b);
}

__global__ __launch_bounds__(192)
void vel_kernel(const float* __restrict__ phi,
                const float* __restrict__ stream,
                float* __restrict__ vel,
                float* __restrict__ vphi,
                float* __restrict__ vstr) {
    const int k4 = threadIdx.x;            // 0..23
    const int jy = threadIdx.y;            // 0..7
    const int jt = blockIdx.x;             // 0..11
    const int i  = blockIdx.y;             // 0..93
    const int b  = blockIdx.z;             // 0..7
    const int j  = jt * 8 + jy;
    if (j >= O) return;
    const int k = k4 * 4;
    const bool full = (k4 != 23);          // tail group: only k=92,93 valid

    const float* P  = phi + (size_t)b * HS;
    const float* s0 = stream + (size_t)b * 3 * HS;
    const float* s1 = s0 + HS;
    const float* s2 = s0 + 2 * HS;

    float pu[4], pv[4], pw[4], su[4], sv[4], sw[4];
    float e[8];

    // ---- phi ----
    ld8(P + rH(i + 1, j + 1), k, e);
    #pragma unroll
    for (int t = 0; t < 4; t++) pu[t] = 0.5f * (e[t + 2] - e[t]);
    ld8(P + rH(i + 1, j + 2), k, e);
    #pragma unroll
    for (int t = 0; t < 4; t++) pv[t] = e[t + 1];
    ld8(P + rH(i + 1, j), k, e);
    #pragma unroll
    for (int t = 0; t < 4; t++) pv[t] = 0.5f * (pv[t] - e[t + 1]);
    ld8(P + rH(i + 2, j + 1), k, e);
    #pragma unroll
    for (int t = 0; t < 4; t++) pw[t] = e[t + 1];
    ld8(P + rH(i, j + 1), k, e);
    #pragma unroll
    for (int t = 0; t < 4; t++) pw[t] = 0.5f * (pw[t] - e[t + 1]);

    // ---- s1 rows ----
    ld8(s1 + rH(i + 2, j + 1), k, e);
    #pragma unroll
    for (int t = 0; t < 4; t++) su[t] = e[t] + e[t + 1];
    ld8(s1 + rH(i + 1, j + 1), k, e);
    #pragma unroll
    for (int t = 0; t < 4; t++) {
        su[t] -= e[t] + e[t + 1];
        sw[t]  = e[t + 1] - e[t + 2];
    }
    ld8(s1 + rH(i, j + 1), k, e);
    #pragma unroll
    for (int t = 0; t < 4; t++) sw[t] += e[t + 1] - e[t + 2];

    // ---- s0 rows ----
    ld8(s0 + rH(i + 1, j + 2), k, e);
    #pragma unroll
    for (int t = 0; t < 4; t++) su[t] -= e[t] + e[t + 1];
    ld8(s0 + rH(i + 1, j + 1), k, e);
    #pragma unroll
    for (int t = 0; t < 4; t++) {
        su[t] += e[t] + e[t + 1];
        sv[t]  = e[t + 2] - e[t + 1];
    }
    ld8(s0 + rH(i + 1, j), k, e);
    #pragma unroll
    for (int t = 0; t < 4; t++) sv[t] += e[t + 2] - e[t + 1];

    // ---- s2 rows ----
    ld8(s2 + rH(i + 2, j), k, e);
    #pragma unroll
    for (int t = 0; t < 4; t++) sv[t] -= e[t + 1];
    ld8(s2 + rH(i + 2, j + 1), k, e);
    #pragma unroll
    for (int t = 0; t < 4; t++) sv[t] -= e[t + 1];
    ld8(s2 + rH(i + 1, j), k, e);
    #pragma unroll
    for (int t = 0; t < 4; t++) sv[t] += e[t + 1];
    ld8(s2 + rH(i + 1, j + 1), k, e);
    #pragma unroll
    for (int t = 0; t < 4; t++) {
        sv[t] += e[t + 1];
        sw[t] -= e[t + 1];
    }
    ld8(s2 + rH(i, j + 2), k, e);
    #pragma unroll
    for (int t = 0; t < 4; t++) sw[t] += e[t + 1];
    ld8(s2 + rH(i, j + 1), k, e);
    #pragma unroll
    for (int t = 0; t < 4; t++) sw[t] -= e[t + 1];
    ld8(s2 + rH(i + 1, j + 2), k, e);
    #pragma unroll
    for (int t = 0; t < 4; t++) sw[t] += e[t + 1];

    #pragma unroll
    for (int t = 0; t < 4; t++) {
        su[t] *= 0.5f; sv[t] *= 0.5f; sw[t] *= 0.5f;
    }

    const size_t o0 = (((size_t)(b * 3) * O + i) * O + j) * O + k;

    st2(vphi + o0,          pu[0], pu[1]);
    st2(vphi + o0 + OS,     pv[0], pv[1]);
    st2(vphi + o0 + 2 * OS, pw[0], pw[1]);
    st2(vstr + o0,          su[0], su[1]);
    st2(vstr + o0 + OS,     sv[0], sv[1]);
    st2(vstr + o0 + 2 * OS, sw[0], sw[1]);
    st2(vel  + o0,          pu[0] + su[0], pu[1] + su[1]);
    st2(vel  + o0 + OS,     pv[0] + sv[0], pv[1] + sv[1]);
    st2(vel  + o0 + 2 * OS, pw[0] + sw[0], pw[1] + sw[1]);

    if (full) {
        st2(vphi + o0 + 2,          pu[2], pu[3]);
        st2(vphi + o0 + OS + 2,     pv[2], pv[3]);
        st2(vphi + o0 + 2 * OS + 2, pw[2], pw[3]);
        st2(vstr + o0 + 2,          su[2], su[3]);
        st2(vstr + o0 + OS + 2,     sv[2], sv[3]);
        st2(vstr + o0 + 2 * OS + 2, sw[2], sw[3]);
        st2(vel  + o0 + 2,          pu[2] + su[2], pu[3] + su[3]);
        st2(vel  + o0 + OS + 2,     pv[2] + sv[2], pv[3] + sv[3]);
        st2(vel  + o0 + 2 * OS + 2, pw[2] + sw[2], pw[3] + sw[3]);
    }
}

// ---------------------------------------------------------------------------
extern "C" void kernel_launch(void* const* d_in, const int* in_sizes, int n_in,
                              void* d_out, int out_size) {
    const float* prev   = (const float*)d_in[0];
    const float* nxt    = (const float*)d_in[1];
    const float* phi    = (const float*)d_in[2];
    const float* stream = (const float*)d_in[3];

    float* out  = (float*)d_out;
    float* corr = out;
    float* vel  = out + CORR_ELEMS;
    float* vphi = vel + VEL_ELEMS;
    float* vstr = vphi + VEL_ELEMS;

    {
        dim3 blk(12, 16, 1);          // 12 float4 z-groups x 16 y rows
        dim3 grd(D, D / 16, 8);       // (x, y-tiles, b)
        corr_kernel<<<grd, blk>>>(prev, nxt, corr);
    }
    {
        dim3 blk(24, 8, 1);           // 24 k-groups x 8 j rows = 192
        dim3 grd(JT, O, 8);           // (j-tile, i, b)
        vel_kernel<<<grd, blk>>>(phi, stream, vel, vphi, vstr);
    }
}

// round 9
// speedup vs baseline: 1.3733x; 1.1594x over previous
#include <cuda_runtime.h>
#include <cstddef>

// ---------------------------------------------------------------------------
// Shapes (fixed):
// prev/next feat : [8, 32, 48, 48, 48] f32
// phi            : [8, 1, 96, 96, 96]  f32
// stream         : [8, 3, 96, 96, 96]  f32
// out (f32, concatenated): corr[8,27,48^3], vel/vphi/vstr [8,3,94^3]
// ---------------------------------------------------------------------------

namespace {
constexpr int C  = 32;
constexpr int D  = 48;
constexpr int SX = D * D;               // 2304
constexpr int SY = D;                   // 48
constexpr long SC  = (long)D * D * D;   // 110592
constexpr long SBF = (long)C * SC;

constexpr int H = 96;
constexpr int O = 94;
constexpr long HS = (long)H * H * H;    // 884736
constexpr long OS = (long)O * O * O;    // 830584

constexpr long CORR_ELEMS = 8L * 27 * SC;
constexpr long VEL_ELEMS  = 8L * 3 * OS;

constexpr int JT = 12;                  // ceil(94/8) j-tiles for vel grid
}

// ---------------------------------------------------------------------------
// Kernel 1: correlation (identical to the proven R1 version, 79us).
// ---------------------------------------------------------------------------
__global__ __launch_bounds__(192)
void corr_kernel(const float* __restrict__ prev,
                 const float* __restrict__ nxt,
                 float* __restrict__ out) {
    const int z4 = threadIdx.x;                       // 0..11
    const int y  = blockIdx.y * blockDim.y + threadIdx.y;
    const int x  = blockIdx.x;
    const int b  = blockIdx.z;
    const int z  = z4 * 4;

    const size_t base = (size_t)b * SBF + (size_t)x * SX + (size_t)y * SY + z;

    bool vx[3], vy[3];
    vx[0] = (x > 0); vx[1] = true; vx[2] = (x < D - 1);
    vy[0] = (y > 0); vy[1] = true; vy[2] = (y < D - 1);

    float4 acc[9];
    #pragma unroll
    for (int d = 0; d < 9; d++) acc[d] = make_float4(0.f, 0.f, 0.f, 0.f);

    #pragma unroll 4
    for (int c = 0; c < C; c++) {
        const size_t cb = base + (size_t)c * SC;
        const float4 p = *reinterpret_cast<const float4*>(prev + cb);
        const float* nb = nxt + cb;
        #pragma unroll
        for (int ix = 0; ix < 3; ix++) {
            #pragma unroll
            for (int iy = 0; iy < 3; iy++) {
                float4 n = make_float4(0.f, 0.f, 0.f, 0.f);
                if (vx[ix] && vy[iy])
                    n = *reinterpret_cast<const float4*>(
                        nb + (ix - 1) * SX + (iy - 1) * SY);
                const int d = ix * 3 + iy;
                acc[d].x += p.x * n.x;
                acc[d].y += p.y * n.y;
                acc[d].z += p.z * n.z;
                acc[d].w += p.w * n.w;
            }
        }
    }

    const float inv = 1.0f / 32.0f;
    const size_t ob = (size_t)b * 27 * SC + (size_t)x * SX + (size_t)y * SY + z;

    #pragma unroll
    for (int d = 0; d < 9; d++) {
        float4 v = acc[d];
        v.x *= inv; v.y *= inv; v.z *= inv; v.w *= inv;

        *reinterpret_cast<float4*>(out + ob + (size_t)(9 + d) * SC) = v;

        float4 vm = v;                      // k=-1: zero z==47
        if (z4 == 11) vm.w = 0.f;
        *reinterpret_cast<float4*>(out + ob + (size_t)d * SC) = vm;

        float4 vp = v;                      // k=+1: zero z==0
        if (z4 == 0) vp.x = 0.f;
        *reinterpret_cast<float4*>(out + ob + (size_t)(18 + d) * SC) = vp;
    }
}

// ---------------------------------------------------------------------------
// Kernel 2: velocities, vectorized + LOW register pressure.
// Restructured into three sequential component passes (u, v, w): each pass
// computes its phi part and stream part, stores its 3 output components,
// then releases registers. Formulas identical to the R6-verified version;
// two stream rows are reloaded across passes (L1 hits).
// Tail group (k4==23) stores only k=92,93. All float4 loads in-bounds
// (max index 884,643 < 884,736 per batch).
// ---------------------------------------------------------------------------
__device__ __forceinline__ size_t rH(int x, int y) {
    return ((size_t)x * H + y) * H;
}

__device__ __forceinline__ void ld8(const float* __restrict__ row, int k,
                                    float e[8]) {
    const float4 a = *reinterpret_cast<const float4*>(row + k);
    const float4 b = *reinterpret_cast<const float4*>(row + k + 4);
    e[0] = a.x; e[1] = a.y; e[2] = a.z; e[3] = a.w;
    e[4] = b.x; e[5] = b.y; e[6] = b.z; e[7] = b.w;
}

__device__ __forceinline__ void st2(float* __restrict__ p, float a, float b) {
    *reinterpret_cast<float2*>(p) = make_float2(a, b);
}

// store 4 values at p[0..3]; tail threads store only the first pair
__device__ __forceinline__ void st4m(float* __restrict__ p, const float v[4],
                                     bool full) {
    st2(p, v[0], v[1]);
    if (full) st2(p + 2, v[2], v[3]);
}

__global__ __launch_bounds__(192, 8)
void vel_kernel(const float* __restrict__ phi,
                const float* __restrict__ stream,
                float* __restrict__ vel,
                float* __restrict__ vphi,
                float* __restrict__ vstr) {
    const int k4 = threadIdx.x;            // 0..23
    const int jy = threadIdx.y;            // 0..7
    const int jt = blockIdx.x;             // 0..11
    const int i  = blockIdx.y;             // 0..93
    const int b  = blockIdx.z;             // 0..7
    const int j  = jt * 8 + jy;
    if (j >= O) return;
    const int k = k4 * 4;
    const bool full = (k4 != 23);          // tail group: only k=92,93 valid

    const float* P  = phi + (size_t)b * HS;
    const float* s0 = stream + (size_t)b * 3 * HS;
    const float* s1 = s0 + HS;
    const float* s2 = s0 + 2 * HS;

    const size_t o0 = (((size_t)(b * 3) * O + i) * O + j) * O + k;

    float e[8];

    // ================= component u =================
    {
        float p4[4], s4[4], o4[4];

        ld8(P + rH(i + 1, j + 1), k, e);
        #pragma unroll
        for (int t = 0; t < 4; t++) p4[t] = 0.5f * (e[t + 2] - e[t]);

        ld8(s1 + rH(i + 2, j + 1), k, e);
        #pragma unroll
        for (int t = 0; t < 4; t++) s4[t] = e[t] + e[t + 1];
        ld8(s1 + rH(i + 1, j + 1), k, e);
        #pragma unroll
        for (int t = 0; t < 4; t++) s4[t] -= e[t] + e[t + 1];
        ld8(s0 + rH(i + 1, j + 2), k, e);
        #pragma unroll
        for (int t = 0; t < 4; t++) s4[t] -= e[t] + e[t + 1];
        ld8(s0 + rH(i + 1, j + 1), k, e);
        #pragma unroll
        for (int t = 0; t < 4; t++) s4[t] = 0.5f * (s4[t] + e[t] + e[t + 1]);

        st4m(vphi + o0, p4, full);
        st4m(vstr + o0, s4, full);
        #pragma unroll
        for (int t = 0; t < 4; t++) o4[t] = p4[t] + s4[t];
        st4m(vel + o0, o4, full);
    }

    // ================= component v =================
    {
        float p4[4], s4[4], o4[4];

        ld8(P + rH(i + 1, j + 2), k, e);
        #pragma unroll
        for (int t = 0; t < 4; t++) p4[t] = e[t + 1];
        ld8(P + rH(i + 1, j), k, e);
        #pragma unroll
        for (int t = 0; t < 4; t++) p4[t] = 0.5f * (p4[t] - e[t + 1]);

        ld8(s0 + rH(i + 1, j + 1), k, e);
        #pragma unroll
        for (int t = 0; t < 4; t++) s4[t] = e[t + 2] - e[t + 1];
        ld8(s0 + rH(i + 1, j), k, e);
        #pragma unroll
        for (int t = 0; t < 4; t++) s4[t] += e[t + 2] - e[t + 1];
        ld8(s2 + rH(i + 2, j), k, e);
        #pragma unroll
        for (int t = 0; t < 4; t++) s4[t] -= e[t + 1];
        ld8(s2 + rH(i + 2, j + 1), k, e);
        #pragma unroll
        for (int t = 0; t < 4; t++) s4[t] -= e[t + 1];
        ld8(s2 + rH(i + 1, j), k, e);
        #pragma unroll
        for (int t = 0; t < 4; t++) s4[t] += e[t + 1];
        ld8(s2 + rH(i + 1, j + 1), k, e);
        #pragma unroll
        for (int t = 0; t < 4; t++) s4[t] = 0.5f * (s4[t] + e[t + 1]);

        st4m(vphi + o0 + OS, p4, full);
        st4m(vstr + o0 + OS, s4, full);
        #pragma unroll
        for (int t = 0; t < 4; t++) o4[t] = p4[t] + s4[t];
        st4m(vel + o0 + OS, o4, full);
    }

    // ================= component w =================
    {
        float p4[4], s4[4], o4[4];

        ld8(P + rH(i + 2, j + 1), k, e);
        #pragma unroll
        for (int t = 0; t < 4; t++) p4[t] = e[t + 1];
        ld8(P + rH(i, j + 1), k, e);
        #pragma unroll
        for (int t = 0; t < 4; t++) p4[t] = 0.5f * (p4[t] - e[t + 1]);

        ld8(s1 + rH(i + 1, j + 1), k, e);
        #pragma unroll
        for (int t = 0; t < 4; t++) s4[t] = e[t + 1] - e[t + 2];
        ld8(s1 + rH(i, j + 1), k, e);
        #pragma unroll
        for (int t = 0; t < 4; t++) s4[t] += e[t + 1] - e[t + 2];
        ld8(s2 + rH(i, j + 2), k, e);
        #pragma unroll
        for (int t = 0; t < 4; t++) s4[t] += e[t + 1];
        ld8(s2 + rH(i, j + 1), k, e);
        #pragma unroll
        for (int t = 0; t < 4; t++) s4[t] -= e[t + 1];
        ld8(s2 + rH(i + 1, j + 2), k, e);
        #pragma unroll
        for (int t = 0; t < 4; t++) s4[t] += e[t + 1];
        ld8(s2 + rH(i + 1, j + 1), k, e);
        #pragma unroll
        for (int t = 0; t < 4; t++) s4[t] = 0.5f * (s4[t] - e[t + 1]);

        st4m(vphi + o0 + 2 * OS, p4, full);
        st4m(vstr + o0 + 2 * OS, s4, full);
        #pragma unroll
        for (int t = 0; t < 4; t++) o4[t] = p4[t] + s4[t];
        st4m(vel + o0 + 2 * OS, o4, full);
    }
}

// ---------------------------------------------------------------------------
extern "C" void kernel_launch(void* const* d_in, const int* in_sizes, int n_in,
                              void* d_out, int out_size) {
    const float* prev   = (const float*)d_in[0];
    const float* nxt    = (const float*)d_in[1];
    const float* phi    = (const float*)d_in[2];
    const float* stream = (const float*)d_in[3];

    float* out  = (float*)d_out;
    float* corr = out;
    float* vel  = out + CORR_ELEMS;
    float* vphi = vel + VEL_ELEMS;
    float* vstr = vphi + VEL_ELEMS;

    {
        dim3 blk(12, 16, 1);          // 12 float4 z-groups x 16 y rows
        dim3 grd(D, D / 16, 8);       // (x, y-tiles, b)
        corr_kernel<<<grd, blk>>>(prev, nxt, corr);
    }
    {
        dim3 blk(24, 8, 1);           // 24 k-groups x 8 j rows = 192
        dim3 grd(JT, O, 8);           // (j-tile, i, b)
        vel_kernel<<<grd, blk>>>(phi, stream, vel, vphi, vstr);
    }
}